// round 8
// baseline (speedup 1.0000x reference)
#include <cuda_runtime.h>
#include <math.h>
#include <stdint.h>

#define NB      4
#define IN_CHAN 128
#define HW      3136
#define HWP     3328      // 26*128 = 13*256 = 52*64
#define OC      32
#define QC      8
#define D       16
#define JSPLIT  14
#define JLEN    (HW / JSPLIT)   // 224
#define TJ      32
#define NT      (JLEN / TJ)     // 7 tiles
#define BN_EPS  1e-5f
#define QPIX    64
#define LOG2E   1.44269504088896340736f

#define SB_STRIDE 20      // 80B rows: float4-aligned, low-conflict frag LDS
#define SP_STRIDE 36      // conflict-free AV A-frag LDS (4g+tg distinct)

// ---------------- scratch (device globals; no allocation allowed) ----------------
// tf32 hi/lo pre-split operands (values already rounded; bits feed mma directly)
__device__ __align__(16) float g_Ah[NB][HWP][D], g_Al[NB][HWP][D];  // log2e*[q+rk ; rq]
__device__ __align__(16) float g_Bh[NB][HWP][D], g_Bl[NB][HWP][D];  // [k ; q]
__device__ __align__(16) float g_Vh[NB][HWP][D], g_Vl[NB][HWP][D];  // v + rv
__device__ __align__(16) float g_pacc[JSPLIT][NB][HWP][D];          // partial sum(e^s * v)
__device__ __align__(16) float g_pl[JSPLIT][NB][HWP];               // partial sum(e^s)

// ---------------- tf32 mma helpers ----------------
__device__ __forceinline__ uint32_t f2tf(float f) {
    uint32_t r; asm("cvt.rna.tf32.f32 %0, %1;" : "=r"(r) : "f"(f)); return r;
}
__device__ __forceinline__ float ex2f(float x) {
    float r; asm("ex2.approx.ftz.f32 %0, %1;" : "=f"(r) : "f"(x)); return r;
}
__device__ __forceinline__ void mma8(float* d, const uint32_t* a, const uint32_t* b) {
    asm("mma.sync.aligned.m16n8k8.row.col.f32.tf32.tf32.f32 "
        "{%0,%1,%2,%3}, {%4,%5,%6,%7}, {%8,%9}, {%0,%1,%2,%3};"
        : "+f"(d[0]), "+f"(d[1]), "+f"(d[2]), "+f"(d[3])
        : "r"(a[0]), "r"(a[1]), "r"(a[2]), "r"(a[3]), "r"(b[0]), "r"(b[1]));
}
__device__ __forceinline__ void tfsplit(float x, uint32_t& hi, uint32_t& lo) {
    hi = f2tf(x);
    lo = f2tf(x - __uint_as_float(hi));
}
__device__ __forceinline__ void tfsplit_f(float x, float& hi, float& lo) {
    uint32_t h, l; tfsplit(x, h, l);
    hi = __uint_as_float(h); lo = __uint_as_float(l);
}

// ======================================================================
// Kernel 1: QKV 1x1 conv + BN + build pre-split A/B/V operand arrays.
// ======================================================================
__global__ __launch_bounds__(256)
void qkv_kernel(const float* __restrict__ x, const float* __restrict__ w,
                const float* __restrict__ bq, const float* __restrict__ gamma,
                const float* __restrict__ beta, const float* __restrict__ mean,
                const float* __restrict__ var,
                const float* __restrict__ rq, const float* __restrict__ rk,
                const float* __restrict__ rv)
{
    __shared__ float sw[IN_CHAN][OC];
    __shared__ float sscale[OC], sbias[OC];
    __shared__ float sacc[2][QPIX][OC + 1];
    __shared__ float sr[QPIX][OC + 1];

    const int tid = threadIdx.x;
    const int p   = tid & (QPIX - 1);
    const int qd  = tid >> 6;

    for (int idx = tid; idx < IN_CHAN * OC; idx += 256) {
        int o = idx & (OC - 1), c = idx >> 5;
        sw[c][o] = w[o * IN_CHAN + c];
    }
    if (tid < OC) {
        float sc = gamma[tid] * rsqrtf(var[tid] + BN_EPS);
        sscale[tid] = sc;
        sbias[tid]  = (bq[tid] - mean[tid]) * sc + beta[tid];
    }
    __syncthreads();

    const int n    = blockIdx.y;
    const int gpix = blockIdx.x * QPIX + p;
    const bool live = (gpix < HW);

    float acc[OC];
    #pragma unroll
    for (int o = 0; o < OC; o++) acc[o] = 0.f;

    if (live) {
        const int cbase = qd * 32;
        const float* xp = x + (size_t)n * IN_CHAN * HW + gpix;
        float xv[2][8];
        #pragma unroll
        for (int u = 0; u < 8; u++)
            xv[0][u] = __ldg(xp + (size_t)(cbase + u) * HW);
        #pragma unroll
        for (int cb = 0; cb < 32; cb += 8) {
            const int cur = (cb >> 3) & 1;
            if (cb + 8 < 32) {
                #pragma unroll
                for (int u = 0; u < 8; u++)
                    xv[1 - cur][u] = __ldg(xp + (size_t)(cbase + cb + 8 + u) * HW);
            }
            #pragma unroll
            for (int u = 0; u < 8; u++) {
                const float xs = xv[cur][u];
                const float* swr = &sw[cbase + cb + u][0];
                #pragma unroll
                for (int o = 0; o < OC; o++)
                    acc[o] = fmaf(xs, swr[o], acc[o]);
            }
        }
    }

    if (qd >= 2) {
        #pragma unroll
        for (int o = 0; o < OC; o++) sacc[qd - 2][p][o] = acc[o];
    }
    __syncthreads();
    if (qd < 2) {
        #pragma unroll
        for (int o = 0; o < OC; o++) acc[o] += sacc[qd][p][o];
        if (qd == 1) {
            #pragma unroll
            for (int o = 0; o < OC; o++) sacc[0][p][o] = acc[o];
        }
    }
    __syncthreads();
    if (qd == 0) {
        #pragma unroll
        for (int o = 0; o < OC; o++) {
            float tot = acc[o] + sacc[0][p][o];
            sr[p][o] = fmaf(tot, sscale[o], sbias[o]);
        }
    }
    __syncthreads();

    float hi8[8], lo8[8], hi16[16], lo16[16];
    if (live) {
        if (qd == 0) {               // A[0..7] = log2e*(q + rk)
            #pragma unroll
            for (int c = 0; c < 8; c++)
                tfsplit_f(LOG2E * (sr[p][c] + __ldg(rk + (size_t)c * HW + gpix)),
                          hi8[c], lo8[c]);
            #pragma unroll
            for (int q4 = 0; q4 < 2; q4++) {
                reinterpret_cast<float4*>(&g_Ah[n][gpix][0])[q4] = reinterpret_cast<float4*>(hi8)[q4];
                reinterpret_cast<float4*>(&g_Al[n][gpix][0])[q4] = reinterpret_cast<float4*>(lo8)[q4];
            }
        } else if (qd == 1) {        // A[8..15] = log2e*rq
            #pragma unroll
            for (int c = 0; c < 8; c++)
                tfsplit_f(LOG2E * __ldg(rq + (size_t)c * HW + gpix), hi8[c], lo8[c]);
            #pragma unroll
            for (int q4 = 0; q4 < 2; q4++) {
                reinterpret_cast<float4*>(&g_Ah[n][gpix][8])[q4] = reinterpret_cast<float4*>(hi8)[q4];
                reinterpret_cast<float4*>(&g_Al[n][gpix][8])[q4] = reinterpret_cast<float4*>(lo8)[q4];
            }
        } else if (qd == 2) {        // B = [k ; q]
            #pragma unroll
            for (int c = 0; c < 8; c++) {
                tfsplit_f(sr[p][QC + c], hi16[c],      lo16[c]);
                tfsplit_f(sr[p][c],      hi16[QC + c], lo16[QC + c]);
            }
            #pragma unroll
            for (int q4 = 0; q4 < 4; q4++) {
                reinterpret_cast<float4*>(&g_Bh[n][gpix][0])[q4] = reinterpret_cast<float4*>(hi16)[q4];
                reinterpret_cast<float4*>(&g_Bl[n][gpix][0])[q4] = reinterpret_cast<float4*>(lo16)[q4];
            }
        } else {                     // V = v + rv
            #pragma unroll
            for (int c = 0; c < 16; c++)
                tfsplit_f(sr[p][2 * QC + c] + __ldg(rv + (size_t)c * HW + gpix),
                          hi16[c], lo16[c]);
            #pragma unroll
            for (int q4 = 0; q4 < 4; q4++) {
                reinterpret_cast<float4*>(&g_Vh[n][gpix][0])[q4] = reinterpret_cast<float4*>(hi16)[q4];
                reinterpret_cast<float4*>(&g_Vl[n][gpix][0])[q4] = reinterpret_cast<float4*>(lo16)[q4];
            }
        }
    } else {
        float4 z = make_float4(0.f, 0.f, 0.f, 0.f);
        if (qd == 0) {
            #pragma unroll
            for (int q4 = 0; q4 < 2; q4++) {
                reinterpret_cast<float4*>(&g_Ah[n][gpix][0])[q4] = z;
                reinterpret_cast<float4*>(&g_Al[n][gpix][0])[q4] = z;
            }
        } else if (qd == 1) {
            #pragma unroll
            for (int q4 = 0; q4 < 2; q4++) {
                reinterpret_cast<float4*>(&g_Ah[n][gpix][8])[q4] = z;
                reinterpret_cast<float4*>(&g_Al[n][gpix][8])[q4] = z;
            }
        } else if (qd == 2) {
            #pragma unroll
            for (int q4 = 0; q4 < 4; q4++) {
                reinterpret_cast<float4*>(&g_Bh[n][gpix][0])[q4] = z;
                reinterpret_cast<float4*>(&g_Bl[n][gpix][0])[q4] = z;
            }
        } else {
            #pragma unroll
            for (int q4 = 0; q4 < 4; q4++) {
                reinterpret_cast<float4*>(&g_Vh[n][gpix][0])[q4] = z;
                reinterpret_cast<float4*>(&g_Vl[n][gpix][0])[q4] = z;
            }
        }
    }
}

// ======================================================================
// Kernel 2: tensor-core attention, pre-split operands, double-buffered
// smem tiles, one __syncthreads per j-tile.
// Block = 128 thr (4 warps) = 128 i-rows x one j-split.
// ======================================================================
__global__ __launch_bounds__(128)
void attn_kernel()
{
    __shared__ __align__(16) float sBh[2][TJ][SB_STRIDE], sBl[2][TJ][SB_STRIDE];
    __shared__ __align__(16) float sVh[2][TJ][SB_STRIDE], sVl[2][TJ][SB_STRIDE];
    __shared__ float sp[128][SP_STRIDE];

    const int tid   = threadIdx.x;
    const int warp  = tid >> 5;
    const int lane  = tid & 31;
    const int g     = lane >> 2;
    const int tg    = lane & 3;
    const int itile = blockIdx.x;
    const int js    = blockIdx.y;
    const int n     = blockIdx.z;
    const int i0    = itile * 128;
    const int wbase = warp * 32;
    const int jbase = js * JLEN;

    const int lr  = tid >> 2;           // coop-load row
    const int lc4 = (tid & 3) * 4;      // coop-load col

    // ---- persistent A fragments straight from pre-split arrays ----
    uint32_t ah[2][2][4], al[2][2][4];
    #pragma unroll
    for (int mg = 0; mg < 2; mg++)
        #pragma unroll
        for (int ks = 0; ks < 2; ks++)
            #pragma unroll
            for (int r = 0; r < 4; r++) {
                int row = i0 + wbase + mg * 16 + g + ((r & 1) ? 8 : 0);
                int col = ks * 8 + tg + ((r & 2) ? 4 : 0);
                ah[mg][ks][r] = __float_as_uint(g_Ah[n][row][col]);
                al[mg][ks][r] = __float_as_uint(g_Al[n][row][col]);
            }

    float co[2][2][4];
    #pragma unroll
    for (int mg = 0; mg < 2; mg++)
        #pragma unroll
        for (int nt = 0; nt < 2; nt++)
            #pragma unroll
            for (int r = 0; r < 4; r++) co[mg][nt][r] = 0.f;
    float L[2][2] = {{0.f, 0.f}, {0.f, 0.f}};

    // ---- prolog: tile 0 into buffer 0 ----
    {
        const float* src = &g_Bh[n][jbase + lr][lc4];
        *reinterpret_cast<float4*>(&sBh[0][lr][lc4]) = *reinterpret_cast<const float4*>(src);
        *reinterpret_cast<float4*>(&sBl[0][lr][lc4]) =
            *reinterpret_cast<const float4*>(&g_Bl[n][jbase + lr][lc4]);
        *reinterpret_cast<float4*>(&sVh[0][lr][lc4]) =
            *reinterpret_cast<const float4*>(&g_Vh[n][jbase + lr][lc4]);
        *reinterpret_cast<float4*>(&sVl[0][lr][lc4]) =
            *reinterpret_cast<const float4*>(&g_Vl[n][jbase + lr][lc4]);
    }
    __syncthreads();

    for (int t = 0; t < NT; t++) {
        const int cur = t & 1;

        // prefetch next tile into registers (overlaps with compute)
        float4 rbh, rbl, rvh, rvl;
        if (t + 1 < NT) {
            const int jn = jbase + (t + 1) * TJ + lr;
            rbh = *reinterpret_cast<const float4*>(&g_Bh[n][jn][lc4]);
            rbl = *reinterpret_cast<const float4*>(&g_Bl[n][jn][lc4]);
            rvh = *reinterpret_cast<const float4*>(&g_Vh[n][jn][lc4]);
            rvl = *reinterpret_cast<const float4*>(&g_Vl[n][jn][lc4]);
        }

        // ---- scores: S[32i x 32j] per warp (x3 compensated) ----
        float cs[2][4][4];
        #pragma unroll
        for (int mg = 0; mg < 2; mg++)
            #pragma unroll
            for (int nt = 0; nt < 4; nt++)
                #pragma unroll
                for (int r = 0; r < 4; r++) cs[mg][nt][r] = 0.f;

        #pragma unroll
        for (int ks = 0; ks < 2; ks++) {
            uint32_t bh[4][2], bl[4][2];
            #pragma unroll
            for (int nt = 0; nt < 4; nt++)
                #pragma unroll
                for (int rr = 0; rr < 2; rr++) {
                    bh[nt][rr] = __float_as_uint(sBh[cur][nt * 8 + g][ks * 8 + tg + rr * 4]);
                    bl[nt][rr] = __float_as_uint(sBl[cur][nt * 8 + g][ks * 8 + tg + rr * 4]);
                }
            #pragma unroll
            for (int mg = 0; mg < 2; mg++)
                #pragma unroll
                for (int nt = 0; nt < 4; nt++) {
                    mma8(cs[mg][nt], ah[mg][ks], bh[nt]);
                    mma8(cs[mg][nt], al[mg][ks], bh[nt]);
                    mma8(cs[mg][nt], ah[mg][ks], bl[nt]);
                }
        }

        // ---- exp2, row sums, stage P ----
        #pragma unroll
        for (int mg = 0; mg < 2; mg++) {
            float s0 = 0.f, s1 = 0.f;
            #pragma unroll
            for (int nt = 0; nt < 4; nt++) {
                float p0 = ex2f(cs[mg][nt][0]);
                float p1 = ex2f(cs[mg][nt][1]);
                float p2 = ex2f(cs[mg][nt][2]);
                float p3 = ex2f(cs[mg][nt][3]);
                s0 += p0 + p1;
                s1 += p2 + p3;
                int r0 = wbase + mg * 16 + g;
                int c  = nt * 8 + 2 * tg;
                *reinterpret_cast<float2*>(&sp[r0][c])     = make_float2(p0, p1);
                *reinterpret_cast<float2*>(&sp[r0 + 8][c]) = make_float2(p2, p3);
            }
            s0 += __shfl_xor_sync(0xffffffffu, s0, 1);
            s0 += __shfl_xor_sync(0xffffffffu, s0, 2);
            s1 += __shfl_xor_sync(0xffffffffu, s1, 1);
            s1 += __shfl_xor_sync(0xffffffffu, s1, 2);
            L[mg][0] += s0;
            L[mg][1] += s1;
        }
        __syncwarp();

        // ---- AV: co += P x V (x3 compensated) ----
        #pragma unroll
        for (int kj = 0; kj < 4; kj++) {
            uint32_t pah[2][4], pal[2][4];
            #pragma unroll
            for (int mg = 0; mg < 2; mg++)
                #pragma unroll
                for (int r = 0; r < 4; r++) {
                    int row = wbase + mg * 16 + g + ((r & 1) ? 8 : 0);
                    int col = kj * 8 + tg + ((r & 2) ? 4 : 0);
                    tfsplit(sp[row][col], pah[mg][r], pal[mg][r]);
                }
            uint32_t vh[2][2], vl[2][2];
            #pragma unroll
            for (int nt = 0; nt < 2; nt++)
                #pragma unroll
                for (int rr = 0; rr < 2; rr++) {
                    vh[nt][rr] = __float_as_uint(sVh[cur][kj * 8 + tg + rr * 4][nt * 8 + g]);
                    vl[nt][rr] = __float_as_uint(sVl[cur][kj * 8 + tg + rr * 4][nt * 8 + g]);
                }
            #pragma unroll
            for (int mg = 0; mg < 2; mg++)
                #pragma unroll
                for (int nt = 0; nt < 2; nt++) {
                    mma8(co[mg][nt], pah[mg], vh[nt]);
                    mma8(co[mg][nt], pal[mg], vh[nt]);
                    mma8(co[mg][nt], pah[mg], vl[nt]);
                }
        }

        // ---- store prefetched tile into the other buffer, single sync ----
        if (t + 1 < NT) {
            const int nxt = 1 - cur;
            *reinterpret_cast<float4*>(&sBh[nxt][lr][lc4]) = rbh;
            *reinterpret_cast<float4*>(&sBl[nxt][lr][lc4]) = rbl;
            *reinterpret_cast<float4*>(&sVh[nxt][lr][lc4]) = rvh;
            *reinterpret_cast<float4*>(&sVl[nxt][lr][lc4]) = rvl;
        }
        __syncthreads();
    }

    // ---- epilogue ----
    #pragma unroll
    for (int mg = 0; mg < 2; mg++)
        #pragma unroll
        for (int nt = 0; nt < 2; nt++) {
            int r0 = i0 + wbase + mg * 16 + g;
            int c  = nt * 8 + 2 * tg;
            *reinterpret_cast<float2*>(&g_pacc[js][n][r0][c]) =
                make_float2(co[mg][nt][0], co[mg][nt][1]);
            *reinterpret_cast<float2*>(&g_pacc[js][n][r0 + 8][c]) =
                make_float2(co[mg][nt][2], co[mg][nt][3]);
        }
    if (tg == 0) {
        #pragma unroll
        for (int mg = 0; mg < 2; mg++) {
            g_pl[js][n][i0 + wbase + mg * 16 + g]     = L[mg][0];
            g_pl[js][n][i0 + wbase + mg * 16 + g + 8] = L[mg][1];
        }
    }
}

// ======================================================================
// Kernel 3: combine j-split partials, normalize, 2x2 avg pool.
// ======================================================================
__global__ void combine_kernel(float* __restrict__ out)
{
    const int idx = blockIdx.x * blockDim.x + threadIdx.x;
    const int TOT = NB * 2 * QC * 28 * 28;
    if (idx >= TOT) return;
    int pw = idx % 28;
    int t  = idx / 28;
    int ph = t % 28; t /= 28;
    int c  = t % (2 * QC);
    int n  = t / (2 * QC);

    float r = 0.f;
    #pragma unroll
    for (int sh = 0; sh < 2; sh++) {
        #pragma unroll
        for (int sw_ = 0; sw_ < 2; sw_++) {
            int i = (2 * ph + sh) * 56 + (2 * pw + sw_);
            float num = 0.f, den = 0.f;
            #pragma unroll
            for (int s = 0; s < JSPLIT; s++) {
                num += g_pacc[s][n][i][c];
                den += g_pl[s][n][i];
            }
            r += num / den;
        }
    }
    out[idx] = 0.25f * r;
}

// ======================================================================
extern "C" void kernel_launch(void* const* d_in, const int* in_sizes, int n_in,
                              void* d_out, int out_size)
{
    const float* x     = (const float*)d_in[0];
    const float* w     = (const float*)d_in[1];
    const float* bq    = (const float*)d_in[2];
    const float* gamma = (const float*)d_in[3];
    const float* beta  = (const float*)d_in[4];
    const float* mean  = (const float*)d_in[5];
    const float* var   = (const float*)d_in[6];
    const float* rq    = (const float*)d_in[7];
    const float* rk    = (const float*)d_in[8];
    const float* rv    = (const float*)d_in[9];
    float* out = (float*)d_out;

    dim3 g1(HWP / QPIX, NB);          // (52, 4)
    qkv_kernel<<<g1, 256>>>(x, w, bq, gamma, beta, mean, var, rq, rk, rv);

    dim3 g2(HWP / 128, JSPLIT, NB);   // (26, 14, 4)
    attn_kernel<<<g2, 128>>>();

    const int TOT = NB * 2 * QC * 28 * 28;
    combine_kernel<<<(TOT + 255) / 256, 256>>>(out);
}

// round 9
// speedup vs baseline: 1.3848x; 1.3848x over previous
#include <cuda_runtime.h>
#include <math.h>
#include <stdint.h>

#define NB      4
#define IN_CHAN 128
#define HW      3136
#define HWP     3328      // 26*128 = 13*256 = 52*64
#define OC      32
#define QC      8
#define D       16
#define JSPLIT  14
#define JLEN    (HW / JSPLIT)   // 224
#define TJ      32
#define NT      (JLEN / TJ)     // 7 tiles
#define BN_EPS  1e-5f
#define QPIX    64
#define LOG2E   1.44269504088896340736f

#define SB_STRIDE 20      // 80B rows: float4-aligned, low-conflict frag LDS
#define SP_STRIDE 36      // conflict-free AV A-frag LDS

// ---------------- scratch (device globals; no allocation allowed) ----------------
__device__ __align__(16) float g_A[NB][HWP][D];                 // log2e*[q+rk ; rq]
__device__ __align__(16) float g_B[NB][HWP][D];                 // [k ; q]
__device__ __align__(16) float g_V[NB][HWP][D];                 // v + rv
__device__ __align__(16) float g_pacc[JSPLIT][NB][HWP][D];      // partial sum(e^s * v)
__device__ __align__(16) float g_pl[JSPLIT][NB][HWP];           // partial sum(e^s)

// ---------------- tf32 mma helpers ----------------
__device__ __forceinline__ uint32_t f2tf(float f) {
    uint32_t r; asm("cvt.rna.tf32.f32 %0, %1;" : "=r"(r) : "f"(f)); return r;
}
__device__ __forceinline__ float ex2f(float x) {
    float r; asm("ex2.approx.ftz.f32 %0, %1;" : "=f"(r) : "f"(x)); return r;
}
__device__ __forceinline__ void mma8(float* d, const uint32_t* a, const uint32_t* b) {
    asm("mma.sync.aligned.m16n8k8.row.col.f32.tf32.tf32.f32 "
        "{%0,%1,%2,%3}, {%4,%5,%6,%7}, {%8,%9}, {%0,%1,%2,%3};"
        : "+f"(d[0]), "+f"(d[1]), "+f"(d[2]), "+f"(d[3])
        : "r"(a[0]), "r"(a[1]), "r"(a[2]), "r"(a[3]), "r"(b[0]), "r"(b[1]));
}
__device__ __forceinline__ void tfsplit(float x, uint32_t& hi, uint32_t& lo) {
    hi = f2tf(x);
    lo = f2tf(x - __uint_as_float(hi));
}

// ======================================================================
// Kernel 1: QKV 1x1 conv + BN + build A/B/V (A pre-scaled by log2e).
// 256 thr / 64 pix, 4-way channel split; all 32 channel loads hoisted
// upfront (MLP=32) to kill serialized load-batch stalls.
// ======================================================================
__global__ __launch_bounds__(256)
void qkv_kernel(const float* __restrict__ x, const float* __restrict__ w,
                const float* __restrict__ bq, const float* __restrict__ gamma,
                const float* __restrict__ beta, const float* __restrict__ mean,
                const float* __restrict__ var,
                const float* __restrict__ rq, const float* __restrict__ rk,
                const float* __restrict__ rv)
{
    __shared__ float sw[IN_CHAN][OC];
    __shared__ float sscale[OC], sbias[OC];
    __shared__ float sacc[2][QPIX][OC + 1];
    __shared__ float sr[QPIX][OC + 1];

    const int tid = threadIdx.x;
    const int p   = tid & (QPIX - 1);
    const int qd  = tid >> 6;

    for (int idx = tid; idx < IN_CHAN * OC; idx += 256) {
        int o = idx & (OC - 1), c = idx >> 5;
        sw[c][o] = w[o * IN_CHAN + c];
    }
    if (tid < OC) {
        float sc = gamma[tid] * rsqrtf(var[tid] + BN_EPS);
        sscale[tid] = sc;
        sbias[tid]  = (bq[tid] - mean[tid]) * sc + beta[tid];
    }
    __syncthreads();

    const int n    = blockIdx.y;
    const int gpix = blockIdx.x * QPIX + p;
    const bool live = (gpix < HW);

    float acc[OC];
    #pragma unroll
    for (int o = 0; o < OC; o++) acc[o] = 0.f;

    if (live) {
        const int cbase = qd * 32;
        const float* xp = x + (size_t)n * IN_CHAN * HW + gpix;
        float xv[32];
        #pragma unroll
        for (int u = 0; u < 32; u++)
            xv[u] = __ldg(xp + (size_t)(cbase + u) * HW);
        #pragma unroll
        for (int u = 0; u < 32; u++) {
            const float xs = xv[u];
            const float* swr = &sw[cbase + u][0];
            #pragma unroll
            for (int o = 0; o < OC; o++)
                acc[o] = fmaf(xs, swr[o], acc[o]);
        }
    }

    if (qd >= 2) {
        #pragma unroll
        for (int o = 0; o < OC; o++) sacc[qd - 2][p][o] = acc[o];
    }
    __syncthreads();
    if (qd < 2) {
        #pragma unroll
        for (int o = 0; o < OC; o++) acc[o] += sacc[qd][p][o];
        if (qd == 1) {
            #pragma unroll
            for (int o = 0; o < OC; o++) sacc[0][p][o] = acc[o];
        }
    }
    __syncthreads();
    if (qd == 0) {
        #pragma unroll
        for (int o = 0; o < OC; o++) {
            float tot = acc[o] + sacc[0][p][o];
            sr[p][o] = fmaf(tot, sscale[o], sbias[o]);
        }
    }
    __syncthreads();

    if (live) {
        if (qd == 0) {               // A[0..7] = log2e*(q + rk)
            float av[8];
            #pragma unroll
            for (int c = 0; c < 8; c++)
                av[c] = LOG2E * (sr[p][c] + __ldg(rk + (size_t)c * HW + gpix));
            reinterpret_cast<float4*>(&g_A[n][gpix][0])[0] = reinterpret_cast<float4*>(av)[0];
            reinterpret_cast<float4*>(&g_A[n][gpix][0])[1] = reinterpret_cast<float4*>(av)[1];
        } else if (qd == 1) {        // A[8..15] = log2e*rq
            float av[8];
            #pragma unroll
            for (int c = 0; c < 8; c++)
                av[c] = LOG2E * __ldg(rq + (size_t)c * HW + gpix);
            reinterpret_cast<float4*>(&g_A[n][gpix][8])[0] = reinterpret_cast<float4*>(av)[0];
            reinterpret_cast<float4*>(&g_A[n][gpix][8])[1] = reinterpret_cast<float4*>(av)[1];
        } else if (qd == 2) {        // B = [k ; q]
            float bv[16];
            #pragma unroll
            for (int c = 0; c < 8; c++) { bv[c] = sr[p][QC + c]; bv[QC + c] = sr[p][c]; }
            #pragma unroll
            for (int q4 = 0; q4 < 4; q4++)
                reinterpret_cast<float4*>(&g_B[n][gpix][0])[q4] = reinterpret_cast<float4*>(bv)[q4];
        } else {                     // V = v + rv
            float vv[16];
            #pragma unroll
            for (int c = 0; c < 16; c++)
                vv[c] = sr[p][2 * QC + c] + __ldg(rv + (size_t)c * HW + gpix);
            #pragma unroll
            for (int q4 = 0; q4 < 4; q4++)
                reinterpret_cast<float4*>(&g_V[n][gpix][0])[q4] = reinterpret_cast<float4*>(vv)[q4];
        }
    } else {
        float4 z = make_float4(0.f, 0.f, 0.f, 0.f);
        if (qd == 0) {
            reinterpret_cast<float4*>(&g_A[n][gpix][0])[0] = z;
            reinterpret_cast<float4*>(&g_A[n][gpix][0])[1] = z;
        } else if (qd == 1) {
            reinterpret_cast<float4*>(&g_A[n][gpix][8])[0] = z;
            reinterpret_cast<float4*>(&g_A[n][gpix][8])[1] = z;
        } else if (qd == 2) {
            #pragma unroll
            for (int q4 = 0; q4 < 4; q4++)
                reinterpret_cast<float4*>(&g_B[n][gpix][0])[q4] = z;
        } else {
            #pragma unroll
            for (int q4 = 0; q4 < 4; q4++)
                reinterpret_cast<float4*>(&g_V[n][gpix][0])[q4] = z;
        }
    }
}

// ======================================================================
// Kernel 2: tensor-core attention.
//   scores: tf32 x3 (compensated)     AV: tf32 x1 (P rounded, l over
//   rounded P so rounding cancels in the softmax normalization)
// B split hi/lo and V rounded ONCE at tile load; inner loops LDS->HMMA.
// ======================================================================
__global__ __launch_bounds__(128)
void attn_kernel()
{
    __shared__ __align__(16) float sBh[TJ][SB_STRIDE], sBl[TJ][SB_STRIDE];
    __shared__ __align__(16) float sVh[TJ][SB_STRIDE];
    __shared__ float sp[128][SP_STRIDE];

    const int tid   = threadIdx.x;
    const int warp  = tid >> 5;
    const int lane  = tid & 31;
    const int g     = lane >> 2;
    const int tg    = lane & 3;
    const int itile = blockIdx.x;
    const int js    = blockIdx.y;
    const int n     = blockIdx.z;
    const int i0    = itile * 128;
    const int wbase = warp * 32;
    const int jbase = js * JLEN;

    const int lr  = tid >> 2;
    const int lc4 = (tid & 3) * 4;

    // ---- persistent A fragments (hi/lo split once) ----
    uint32_t ah[2][2][4], al[2][2][4];
    #pragma unroll
    for (int mg = 0; mg < 2; mg++)
        #pragma unroll
        for (int ks = 0; ks < 2; ks++)
            #pragma unroll
            for (int r = 0; r < 4; r++) {
                int row = i0 + wbase + mg * 16 + g + ((r & 1) ? 8 : 0);
                int col = ks * 8 + tg + ((r & 2) ? 4 : 0);
                tfsplit(g_A[n][row][col], ah[mg][ks][r], al[mg][ks][r]);
            }

    float co[2][2][4];
    #pragma unroll
    for (int mg = 0; mg < 2; mg++)
        #pragma unroll
        for (int nt = 0; nt < 2; nt++)
            #pragma unroll
            for (int r = 0; r < 4; r++) co[mg][nt][r] = 0.f;
    float L[2][2] = {{0.f, 0.f}, {0.f, 0.f}};

    for (int t = 0; t < NT; t++) {
        const int j0 = jbase + t * TJ;
        {   // tile load + split/round at load point (4 elems/thread)
            float4 b = *reinterpret_cast<const float4*>(&g_B[n][j0 + lr][lc4]);
            float4 v = *reinterpret_cast<const float4*>(&g_V[n][j0 + lr][lc4]);
            uint32_t h, l;
            tfsplit(b.x, h, l); sBh[lr][lc4+0] = __uint_as_float(h); sBl[lr][lc4+0] = __uint_as_float(l);
            tfsplit(b.y, h, l); sBh[lr][lc4+1] = __uint_as_float(h); sBl[lr][lc4+1] = __uint_as_float(l);
            tfsplit(b.z, h, l); sBh[lr][lc4+2] = __uint_as_float(h); sBl[lr][lc4+2] = __uint_as_float(l);
            tfsplit(b.w, h, l); sBh[lr][lc4+3] = __uint_as_float(h); sBl[lr][lc4+3] = __uint_as_float(l);
            sVh[lr][lc4+0] = __uint_as_float(f2tf(v.x));
            sVh[lr][lc4+1] = __uint_as_float(f2tf(v.y));
            sVh[lr][lc4+2] = __uint_as_float(f2tf(v.z));
            sVh[lr][lc4+3] = __uint_as_float(f2tf(v.w));
        }
        __syncthreads();

        // ---- scores: S[32i x 32j] per warp (x3 compensated) ----
        float cs[2][4][4];
        #pragma unroll
        for (int mg = 0; mg < 2; mg++)
            #pragma unroll
            for (int nt = 0; nt < 4; nt++)
                #pragma unroll
                for (int r = 0; r < 4; r++) cs[mg][nt][r] = 0.f;

        #pragma unroll
        for (int ks = 0; ks < 2; ks++) {
            uint32_t bh[4][2], bl[4][2];
            #pragma unroll
            for (int nt = 0; nt < 4; nt++)
                #pragma unroll
                for (int rr = 0; rr < 2; rr++) {
                    bh[nt][rr] = __float_as_uint(sBh[nt * 8 + g][ks * 8 + tg + rr * 4]);
                    bl[nt][rr] = __float_as_uint(sBl[nt * 8 + g][ks * 8 + tg + rr * 4]);
                }
            #pragma unroll
            for (int mg = 0; mg < 2; mg++)
                #pragma unroll
                for (int nt = 0; nt < 4; nt++) {
                    mma8(cs[mg][nt], ah[mg][ks], bh[nt]);
                    mma8(cs[mg][nt], al[mg][ks], bh[nt]);
                    mma8(cs[mg][nt], ah[mg][ks], bl[nt]);
                }
        }

        // ---- exp2 -> round P to tf32 -> row sums over ROUNDED P -> stage ----
        #pragma unroll
        for (int mg = 0; mg < 2; mg++) {
            float s0 = 0.f, s1 = 0.f;
            #pragma unroll
            for (int nt = 0; nt < 4; nt++) {
                float p0 = __uint_as_float(f2tf(ex2f(cs[mg][nt][0])));
                float p1 = __uint_as_float(f2tf(ex2f(cs[mg][nt][1])));
                float p2 = __uint_as_float(f2tf(ex2f(cs[mg][nt][2])));
                float p3 = __uint_as_float(f2tf(ex2f(cs[mg][nt][3])));
                s0 += p0 + p1;
                s1 += p2 + p3;
                int r0 = wbase + mg * 16 + g;
                int c  = nt * 8 + 2 * tg;
                *reinterpret_cast<float2*>(&sp[r0][c])     = make_float2(p0, p1);
                *reinterpret_cast<float2*>(&sp[r0 + 8][c]) = make_float2(p2, p3);
            }
            s0 += __shfl_xor_sync(0xffffffffu, s0, 1);
            s0 += __shfl_xor_sync(0xffffffffu, s0, 2);
            s1 += __shfl_xor_sync(0xffffffffu, s1, 1);
            s1 += __shfl_xor_sync(0xffffffffu, s1, 2);
            L[mg][0] += s0;
            L[mg][1] += s1;
        }
        __syncwarp();

        // ---- AV: co += P x V, plain tf32 (x1) ----
        #pragma unroll
        for (int kj = 0; kj < 4; kj++) {
            uint32_t pah[2][4];
            #pragma unroll
            for (int mg = 0; mg < 2; mg++)
                #pragma unroll
                for (int r = 0; r < 4; r++) {
                    int row = wbase + mg * 16 + g + ((r & 1) ? 8 : 0);
                    int col = kj * 8 + tg + ((r & 2) ? 4 : 0);
                    pah[mg][r] = __float_as_uint(sp[row][col]);
                }
            uint32_t vh[2][2];
            #pragma unroll
            for (int nt = 0; nt < 2; nt++)
                #pragma unroll
                for (int rr = 0; rr < 2; rr++)
                    vh[nt][rr] = __float_as_uint(sVh[kj * 8 + tg + rr * 4][nt * 8 + g]);
            #pragma unroll
            for (int mg = 0; mg < 2; mg++)
                #pragma unroll
                for (int nt = 0; nt < 2; nt++)
                    mma8(co[mg][nt], pah[mg], vh[nt]);
        }
        __syncthreads();
    }

    // ---- epilogue ----
    #pragma unroll
    for (int mg = 0; mg < 2; mg++)
        #pragma unroll
        for (int nt = 0; nt < 2; nt++) {
            int r0 = i0 + wbase + mg * 16 + g;
            int c  = nt * 8 + 2 * tg;
            *reinterpret_cast<float2*>(&g_pacc[js][n][r0][c]) =
                make_float2(co[mg][nt][0], co[mg][nt][1]);
            *reinterpret_cast<float2*>(&g_pacc[js][n][r0 + 8][c]) =
                make_float2(co[mg][nt][2], co[mg][nt][3]);
        }
    if (tg == 0) {
        #pragma unroll
        for (int mg = 0; mg < 2; mg++) {
            g_pl[js][n][i0 + wbase + mg * 16 + g]     = L[mg][0];
            g_pl[js][n][i0 + wbase + mg * 16 + g + 8] = L[mg][1];
        }
    }
}

// ======================================================================
// Kernel 3: combine. 4 threads per output element (one per pooled pixel),
// shfl-reduce -> 4x more blocks in flight than R8.
// ======================================================================
__global__ void combine_kernel(float* __restrict__ out)
{
    const int TOT  = NB * 2 * QC * 28 * 28;
    const int gidx = blockIdx.x * blockDim.x + threadIdx.x;
    if (gidx >= TOT * 4) return;
    const int e  = gidx >> 2;
    const int px = gidx & 3;

    int pw = e % 28;
    int t  = e / 28;
    int ph = t % 28; t /= 28;
    int c  = t % (2 * QC);
    int n  = t / (2 * QC);

    const int i = (2 * ph + (px >> 1)) * 56 + 2 * pw + (px & 1);

    float num = 0.f, den = 0.f;
    #pragma unroll
    for (int s = 0; s < JSPLIT; s++) {
        num += g_pacc[s][n][i][c];
        den += g_pl[s][n][i];
    }
    float r = num / den;
    r += __shfl_xor_sync(0xffffffffu, r, 1);
    r += __shfl_xor_sync(0xffffffffu, r, 2);
    if (px == 0) out[e] = 0.25f * r;
}

// ======================================================================
extern "C" void kernel_launch(void* const* d_in, const int* in_sizes, int n_in,
                              void* d_out, int out_size)
{
    const float* x     = (const float*)d_in[0];
    const float* w     = (const float*)d_in[1];
    const float* bq    = (const float*)d_in[2];
    const float* gamma = (const float*)d_in[3];
    const float* beta  = (const float*)d_in[4];
    const float* mean  = (const float*)d_in[5];
    const float* var   = (const float*)d_in[6];
    const float* rq    = (const float*)d_in[7];
    const float* rk    = (const float*)d_in[8];
    const float* rv    = (const float*)d_in[9];
    float* out = (float*)d_out;

    dim3 g1(HWP / QPIX, NB);          // (52, 4)
    qkv_kernel<<<g1, 256>>>(x, w, bq, gamma, beta, mean, var, rq, rk, rv);

    dim3 g2(HWP / 128, JSPLIT, NB);   // (26, 14, 4)
    attn_kernel<<<g2, 128>>>();

    const int TOT = NB * 2 * QC * 28 * 28;
    combine_kernel<<<(TOT * 4 + 255) / 256, 256>>>(out);
}